// round 10
// baseline (speedup 1.0000x reference)
#include <cuda_runtime.h>
#include <cuda_fp16.h>

#define TSTEPS 30
#define BLOCK  64
#define NBATCH 262144

// per-combo smem floats (all fp32): D=1 -> 16(wih)+80(whh)+32(bias) = 128
//                                   D=10 -> 160+80+32 = 272
constexpr int WTOT = 256 + 8*272;     // 2432 floats = 9728 B

typedef unsigned long long u64;
typedef unsigned int       u32;

// ---------- packed fp32x2 helpers (sm_103a FFMA2 path) ----------
__device__ __forceinline__ u64 ffma2(u64 a, u64 b, u64 c) {
    u64 d; asm("fma.rn.f32x2 %0, %1, %2, %3;" : "=l"(d) : "l"(a), "l"(b), "l"(c)); return d;
}
__device__ __forceinline__ u64 splat2(float v) {
    u64 d; asm("mov.b64 %0, {%1, %1};" : "=l"(d) : "f"(v)); return d;
}
__device__ __forceinline__ u64 pack2(float x, float y) {
    u64 d; asm("mov.b64 %0, {%1, %2};" : "=l"(d) : "f"(x), "f"(y)); return d;
}
__device__ __forceinline__ float2 unpack2(u64 v) {
    float2 r; asm("mov.b64 {%0, %1}, %2;" : "=f"(r.x), "=f"(r.y) : "l"(v)); return r;
}
__device__ __forceinline__ float tanhfast(float x){ float r; asm("tanh.approx.f32 %0, %1;" : "=f"(r) : "f"(x)); return r; }

__device__ __forceinline__ int comboOff(int c){ return c < 2 ? c*128 : 256 + (c-2)*272; }

union H4 { u64 u; u32 w[2]; __half2 h[2]; };
union H2 { u32 u; __half2 h; };
__device__ __forceinline__ u64 h4pack(__half2 a, __half2 b){ H4 t; t.h[0]=a; t.h[1]=b; return t.u; }
__device__ __forceinline__ u32 h2pack(float x, float y){ H2 t; t.h = __floats2half2_rn(x,y); return t.u; }
__device__ __forceinline__ float2 h2f(u32 v){ H2 t; t.u = v; return __half22float2(t.h); }

// Slot order (rz-merged): s=2u+g, g in {r,z}, unit u (s<10); s=10..14 n-gate; s=15 pad.
// r/z rows scaled 0.5 (gi+gh merged): sig(v)=0.5+0.5*tanh(v/2); n rows unscaled.

// ---------- one GRU timestep: EVERYTHING streamed from smem (broadcast LDS.128):
// wih fp32 (4/k), whh fp32 (20), biases (6). No large register arrays -> no spill. ----------
template<int D>
__device__ __forceinline__ void gru_step(const float* __restrict__ wbase,
                                         const float* xin, float* h)
{
    const float4* wih4 = (const float4*)wbase;
    const float4* whh4 = (const float4*)(wbase + 16*D);
    const float4* bg4  = (const float4*)(wbase + 16*D + 80);
    const float4* bh4  = (const float4*)(wbase + 16*D + 96);
    u64 A[5], Gn[3], Hn[3];
    {   // accumulator init from smem biases
        float4 c0 = bg4[0], c1 = bg4[1], c2 = bg4[2], c3 = bg4[3];
        A[0] = pack2(c0.x,c0.y); A[1] = pack2(c0.z,c0.w);
        A[2] = pack2(c1.x,c1.y); A[3] = pack2(c1.z,c1.w);
        A[4] = pack2(c2.x,c2.y);
        Gn[0] = pack2(c2.z,c2.w); Gn[1] = pack2(c3.x,c3.y); Gn[2] = pack2(c3.z,c3.w);
        float4 d2 = bh4[2], d3 = bh4[3];
        Hn[0] = pack2(d2.z,d2.w); Hn[1] = pack2(d3.x,d3.y); Hn[2] = pack2(d3.z,d3.w);
    }
#pragma unroll
    for (int k = 0; k < D; ++k) {
        u64 xs = splat2(xin[k]);
        float4 w0 = wih4[k*4+0], w1 = wih4[k*4+1], w2 = wih4[k*4+2], w3 = wih4[k*4+3];
        A[0]  = ffma2(pack2(w0.x,w0.y), xs, A[0]);
        A[1]  = ffma2(pack2(w0.z,w0.w), xs, A[1]);
        A[2]  = ffma2(pack2(w1.x,w1.y), xs, A[2]);
        A[3]  = ffma2(pack2(w1.z,w1.w), xs, A[3]);
        A[4]  = ffma2(pack2(w2.x,w2.y), xs, A[4]);
        Gn[0] = ffma2(pack2(w2.z,w2.w), xs, Gn[0]);
        Gn[1] = ffma2(pack2(w3.x,w3.y), xs, Gn[1]);
        Gn[2] = ffma2(pack2(w3.z,w3.w), xs, Gn[2]);
    }
#pragma unroll
    for (int k = 0; k < 5; ++k) {
        u64 hs = splat2(h[k]);
        float4 w0 = whh4[k*4+0], w1 = whh4[k*4+1], w2 = whh4[k*4+2], w3 = whh4[k*4+3];
        A[0]  = ffma2(pack2(w0.x,w0.y), hs, A[0]);
        A[1]  = ffma2(pack2(w0.z,w0.w), hs, A[1]);
        A[2]  = ffma2(pack2(w1.x,w1.y), hs, A[2]);
        A[3]  = ffma2(pack2(w1.z,w1.w), hs, A[3]);
        A[4]  = ffma2(pack2(w2.x,w2.y), hs, A[4]);
        Hn[0] = ffma2(pack2(w2.z,w2.w), hs, Hn[0]);
        Hn[1] = ffma2(pack2(w3.x,w3.y), hs, Hn[1]);
        Hn[2] = ffma2(pack2(w3.z,w3.w), hs, Hn[2]);
    }
    float gn[6], hn[6];
#pragma unroll
    for (int p = 0; p < 3; ++p) {
        float2 a = unpack2(Gn[p]); gn[2*p] = a.x; gn[2*p+1] = a.y;
        float2 c = unpack2(Hn[p]); hn[2*p] = c.x; hn[2*p+1] = c.y;
    }
#pragma unroll
    for (int u = 0; u < 5; ++u) {
        float2 rz = unpack2(A[u]);                   // pre-scaled by 0.5
        float r  = fmaf(0.5f, tanhfast(rz.x), 0.5f);
        float z  = fmaf(0.5f, tanhfast(rz.y), 0.5f);
        float nn = tanhfast(fmaf(r, hn[u], gn[u]));
        h[u] = fmaf(z, h[u] - nn, nn);
    }
}

// fp16 entry: smem uint4 (f0..f4,b0..b2) + local u32 (b3,b4) -> 10 floats
__device__ __forceinline__ void cvt_in(uint4 q, u32 rc, float* xin)
{
    float2 p0 = h2f(q.x);
    float2 p1 = h2f(q.y);
    float2 p2 = h2f(q.z);
    float2 p3 = h2f(q.w);
    float2 p4 = h2f(rc);
    xin[0]=p0.x; xin[1]=p0.y; xin[2]=p1.x; xin[3]=p1.y; xin[4]=p2.x;
    xin[5]=p2.y; xin[6]=p3.x; xin[7]=p3.y; xin[8]=p4.x; xin[9]=p4.y;
}

// merge fwd-staged (fa = f0..f3, fcu = {f4,_}) with bwd h -> entry
__device__ __forceinline__ void pack_entry(const float* hb, u64 fa, u32 fcu,
                                           uint4& oq, u32& oc)
{
    H4 t; t.u = fa;
    H2 fc; fc.u = fcu;
    oq.x = t.w[0];
    oq.y = t.w[1];
    H2 z; z.h = __halves2half2(__low2half(fc.h), __float2half_rn(hb[0]));
    oq.z = z.u;
    oq.w = h2pack(hb[1], hb[2]);
    oc   = h2pack(hb[3], hb[4]);
}

__global__ void __launch_bounds__(BLOCK, 5)
gru_kernel(const float* __restrict__ x,
           const float* __restrict__ wih0, const float* __restrict__ whh0,
           const float* __restrict__ bih0, const float* __restrict__ bhh0,
           const float* __restrict__ wihU, const float* __restrict__ whhU,
           const float* __restrict__ bihU, const float* __restrict__ bhhU,
           float* __restrict__ out)
{
    extern __shared__ float smem[];
    float* sw   = smem;                                   // [WTOT] prepped weights (fp32)
    uint4* bufQ = (uint4*)(smem + WTOT);                  // [T*BLOCK] (f0..f4 + b0..b2) fp16
    const int tid = threadIdx.x;

    // ---- cooperative weight prep: transpose to slot layout, pre-scale, merge biases ----
    for (int c = 0; c < 10; ++c) {
        int l = c >> 1, d = c & 1;
        int D = l ? 10 : 1;
        float* w = sw + comboOff(c);
        for (int i = tid; i < 16*D; i += BLOCK) {           // wihT[k][slot]
            int k = i >> 4, s = i & 15;
            float v = 0.f;
            if (s < 15) {
                int  j  = (s < 10) ? ((s & 1)*5 + (s >> 1)) : s;
                float sc = (s < 10) ? 0.5f : 1.0f;
                v = sc * (l == 0 ? wih0[d*15 + j]
                                 : wihU[(((l-1)*2 + d)*15 + j)*10 + k]);
            }
            w[i] = v;
        }
        float* wh = w + 16*D;
        for (int i = tid; i < 80; i += BLOCK) {             // whhT[k][slot]
            int k = i >> 4, s = i & 15;
            float v = 0.f;
            if (s < 15) {
                int  j  = (s < 10) ? ((s & 1)*5 + (s >> 1)) : s;
                float sc = (s < 10) ? 0.5f : 1.0f;
                v = sc * (l == 0 ? whh0[(d*15 + j)*5 + k]
                                 : whhU[(((l-1)*2 + d)*15 + j)*5 + k]);
            }
            wh[i] = v;
        }
        float* bg = wh + 80;                                // gi-side bias
        for (int s = tid; s < 16; s += BLOCK) {
            float v = 0.f;
            if (s < 15) {
                int  j  = (s < 10) ? ((s & 1)*5 + (s >> 1)) : s;
                float sc = (s < 10) ? 0.5f : 1.0f;
                float bi = l == 0 ? bih0[d*15 + j] : bihU[((l-1)*2 + d)*15 + j];
                float bh = l == 0 ? bhh0[d*15 + j] : bhhU[((l-1)*2 + d)*15 + j];
                v = sc * (s < 10 ? (bi + bh) : bi);
            }
            bg[s] = v;
        }
        float* bh2 = bg + 16;                               // gh-side n bias
        for (int s = tid; s < 16; s += BLOCK) {
            float v = 0.f;
            if (s >= 10 && s < 15)
                v = l == 0 ? bhh0[d*15 + s] : bhhU[((l-1)*2 + d)*15 + s];
            bh2[s] = v;
        }
    }
    __syncthreads();
    // buffer slots are thread-private from here on; no further syncs needed

    const int b = blockIdx.x * BLOCK + tid;
    const float* xrow = x + (size_t)b * TSTEPS;

    float h[5];
    u64 fscrA[TSTEPS];        // local: fwd staging (f0..f3) fp16
    u32 fscrC[TSTEPS];        // local: fwd staging (f4,pad) fp16
    u32 lbufC[TSTEPS];        // local: entry field (b3,b4) fp16

    // ===== layer 0 (D=1): fwd -> fscr, bwd -> merged write to bufQ + lbufC =====
    {
        const float* w = sw + comboOff(0);
#pragma unroll
        for (int u = 0; u < 5; ++u) h[u] = 0.f;
#pragma unroll 1
        for (int t = 0; t < TSTEPS; ++t) {
            float xin[1] = { xrow[t] };
            gru_step<1>(w, xin, h);
            fscrA[t] = h4pack(__floats2half2_rn(h[0], h[1]), __floats2half2_rn(h[2], h[3]));
            fscrC[t] = h2pack(h[4], 0.f);
        }
    }
    {
        const float* w = sw + comboOff(1);
#pragma unroll
        for (int u = 0; u < 5; ++u) h[u] = 0.f;
#pragma unroll 1
        for (int tt = 0; tt < TSTEPS; ++tt) {
            int t = TSTEPS-1-tt;
            u64 fa = fscrA[t]; u32 fc = fscrC[t];          // early load (cover latency)
            float xin[1] = { xrow[t] };
            gru_step<1>(w, xin, h);
            uint4 oq; u32 oc;
            pack_entry(h, fa, fc, oq, oc);
            bufQ[t*BLOCK+tid] = oq; lbufC[t] = oc;
        }
    }

    // ===== layers 1..3: fwd stages into fscr, bwd overwrites entries in place =====
#pragma unroll 1
    for (int l = 1; l < 4; ++l) {
        {   // fwd: lbufC prefetched one step ahead
            const float* w = sw + comboOff(2*l);
#pragma unroll
            for (int u = 0; u < 5; ++u) h[u] = 0.f;
            u32 rc = lbufC[0];
#pragma unroll 1
            for (int t = 0; t < TSTEPS; ++t) {
                u32 cc = rc;
                rc = lbufC[t+1 < TSTEPS ? t+1 : TSTEPS-1];
                float xin[10];
                cvt_in(bufQ[t*BLOCK+tid], cc, xin);
                gru_step<10>(w, xin, h);
                fscrA[t] = h4pack(__floats2half2_rn(h[0], h[1]), __floats2half2_rn(h[2], h[3]));
                fscrC[t] = h2pack(h[4], 0.f);
            }
        }
        {   // bwd: lbufC + fscr prefetched one step ahead
            const float* w = sw + comboOff(2*l+1);
#pragma unroll
            for (int u = 0; u < 5; ++u) h[u] = 0.f;
            u32 rc = lbufC[TSTEPS-1];
#pragma unroll 1
            for (int tt = 0; tt < TSTEPS; ++tt) {
                int t = TSTEPS-1-tt;
                u32 cc = rc;
                rc = lbufC[t > 0 ? t-1 : 0];
                u64 fa = fscrA[t]; u32 fc = fscrC[t];
                float xin[10];
                cvt_in(bufQ[t*BLOCK+tid], cc, xin);
                gru_step<10>(w, xin, h);
                uint4 oq; u32 oc;
                pack_entry(h, fa, fc, oq, oc);
                bufQ[t*BLOCK+tid] = oq; lbufC[t] = oc;
            }
        }
    }

    // ===== layer 4: fwd full (keep final h only); bwd = ONE step at t=T-1 =====
    float hf[5];
    {
        const float* w = sw + comboOff(8);
#pragma unroll
        for (int u = 0; u < 5; ++u) h[u] = 0.f;
        u32 rc = lbufC[0];
#pragma unroll 1
        for (int t = 0; t < TSTEPS; ++t) {
            u32 cc = rc;
            rc = lbufC[t+1 < TSTEPS ? t+1 : TSTEPS-1];
            float xin[10];
            cvt_in(bufQ[t*BLOCK+tid], cc, xin);
            gru_step<10>(w, xin, h);
        }
#pragma unroll
        for (int u = 0; u < 5; ++u) hf[u] = h[u];
    }
    {
        const float* w = sw + comboOff(9);
#pragma unroll
        for (int u = 0; u < 5; ++u) h[u] = 0.f;
        float xin[10];
        int t = TSTEPS-1;
        cvt_in(bufQ[t*BLOCK+tid], lbufC[t], xin);
        gru_step<10>(w, xin, h);
    }

    float2* o2 = (float2*)(out + (size_t)b*10);
    o2[0] = make_float2(hf[0], hf[1]);
    o2[1] = make_float2(hf[2], hf[3]);
    o2[2] = make_float2(hf[4], h[0]);
    o2[3] = make_float2(h[1],  h[2]);
    o2[4] = make_float2(h[3],  h[4]);
}

extern "C" void kernel_launch(void* const* d_in, const int* in_sizes, int n_in,
                              void* d_out, int out_size)
{
    (void)in_sizes; (void)n_in; (void)out_size;
    // 9728 (fp32 weights) + 30*64*16 (bufQ) = 40448 B -> 5 blocks/SM (202 KB), L1D ~26 KB
    const size_t smem = (size_t)WTOT*4 + (size_t)TSTEPS*BLOCK*16;
    cudaFuncSetAttribute(gru_kernel, cudaFuncAttributeMaxDynamicSharedMemorySize, (int)smem);
    gru_kernel<<<NBATCH/BLOCK, BLOCK, smem>>>(
        (const float*)d_in[0],
        (const float*)d_in[1], (const float*)d_in[2],
        (const float*)d_in[3], (const float*)d_in[4],
        (const float*)d_in[5], (const float*)d_in[6],
        (const float*)d_in[7], (const float*)d_in[8],
        (float*)d_out);
}

// round 11
// speedup vs baseline: 1.9573x; 1.9573x over previous
#include <cuda_runtime.h>
#include <cuda_fp16.h>

#define TSTEPS 30
#define BLOCK  64
#define NBATCH 262144

constexpr int WTOT = 2432;                       // prepped weight floats in smem

typedef unsigned long long u64;
typedef unsigned int       u32;

// ---------- packed fp32x2 helpers (sm_103a FFMA2 path) ----------
__device__ __forceinline__ u64 ffma2(u64 a, u64 b, u64 c) {
    u64 d; asm("fma.rn.f32x2 %0, %1, %2, %3;" : "=l"(d) : "l"(a), "l"(b), "l"(c)); return d;
}
__device__ __forceinline__ u64 splat2(float v) {
    u64 d; asm("mov.b64 %0, {%1, %1};" : "=l"(d) : "f"(v)); return d;
}
__device__ __forceinline__ u64 pack2(float x, float y) {
    u64 d; asm("mov.b64 %0, {%1, %2};" : "=l"(d) : "f"(x), "f"(y)); return d;
}
__device__ __forceinline__ float2 unpack2(u64 v) {
    float2 r; asm("mov.b64 {%0, %1}, %2;" : "=f"(r.x), "=f"(r.y) : "l"(v)); return r;
}
__device__ __forceinline__ float tanhfast(float x){ float r; asm("tanh.approx.f32 %0, %1;" : "=f"(r) : "f"(x)); return r; }

__device__ __forceinline__ int comboOff(int c){ return c < 2 ? c*128 : 256 + (c-2)*272; }

union H4 { u64 u; u32 w[2]; __half2 h[2]; };
union H2 { u32 u; __half2 h; };
__device__ __forceinline__ u64 h4pack(__half2 a, __half2 b){ H4 t; t.h[0]=a; t.h[1]=b; return t.u; }
__device__ __forceinline__ u32 h2pack(float x, float y){ H2 t; t.h = __floats2half2_rn(x,y); return t.u; }

// Slot order (rz-merged): s=2u+g, g in {r,z}, unit u (s<10); s=10..14 n-gate; s=15 pad.
// r/z rows scaled 0.5 (gi+gh merged): sig(v)=0.5+0.5*tanh(v/2); n rows unscaled.

// ---------- per-direction constants: W_hh (5x16) + biases in registers ----------
__device__ __forceinline__ void load_dir(const float* wbase, int D,
                                         u64* whhr, u64* bA, u64* bGn, u64* bHn)
{
    const float4* wh4 = (const float4*)(wbase + 16*D);
#pragma unroll
    for (int k = 0; k < 5; ++k)
#pragma unroll
        for (int qq = 0; qq < 4; ++qq) {
            float4 a = wh4[k*4+qq];
            whhr[k*8+qq*2+0] = pack2(a.x, a.y);
            whhr[k*8+qq*2+1] = pack2(a.z, a.w);
        }
    const float4* b4 = (const float4*)(wbase + 16*D + 80);   // gi-side bias
    float4 c0 = b4[0], c1 = b4[1], c2 = b4[2], c3 = b4[3];
    bA[0] = pack2(c0.x,c0.y); bA[1] = pack2(c0.z,c0.w);
    bA[2] = pack2(c1.x,c1.y); bA[3] = pack2(c1.z,c1.w);
    bA[4] = pack2(c2.x,c2.y);
    bGn[0] = pack2(c2.z,c2.w); bGn[1] = pack2(c3.x,c3.y); bGn[2] = pack2(c3.z,c3.w);
    const float4* b5 = (const float4*)(wbase + 16*D + 96);   // gh-side n bias
    float4 d2 = b5[2], d3 = b5[3];
    bHn[0] = pack2(d2.z,d2.w); bHn[1] = pack2(d3.x,d3.y); bHn[2] = pack2(d3.z,d3.w);
}

// ---------- one GRU timestep: wih streamed from smem (broadcast LDS.128),
// W_hh + biases register-resident ----------
template<int D>
__device__ __forceinline__ void gru_step(const float4* __restrict__ wih4,
                                         const u64* whhr, const u64* bA,
                                         const u64* bGn, const u64* bHn,
                                         const float* xin, float* h)
{
    u64 A[5], Gn[3], Hn[3];
#pragma unroll
    for (int p = 0; p < 5; ++p) A[p] = bA[p];
#pragma unroll
    for (int p = 0; p < 3; ++p) { Gn[p] = bGn[p]; Hn[p] = bHn[p]; }
#pragma unroll
    for (int k = 0; k < D; ++k) {
        u64 xs = splat2(xin[k]);
        float4 w0 = wih4[k*4+0], w1 = wih4[k*4+1], w2 = wih4[k*4+2], w3 = wih4[k*4+3];
        A[0]  = ffma2(pack2(w0.x,w0.y), xs, A[0]);
        A[1]  = ffma2(pack2(w0.z,w0.w), xs, A[1]);
        A[2]  = ffma2(pack2(w1.x,w1.y), xs, A[2]);
        A[3]  = ffma2(pack2(w1.z,w1.w), xs, A[3]);
        A[4]  = ffma2(pack2(w2.x,w2.y), xs, A[4]);
        Gn[0] = ffma2(pack2(w2.z,w2.w), xs, Gn[0]);
        Gn[1] = ffma2(pack2(w3.x,w3.y), xs, Gn[1]);
        Gn[2] = ffma2(pack2(w3.z,w3.w), xs, Gn[2]);
    }
#pragma unroll
    for (int k = 0; k < 5; ++k) {
        u64 hs = splat2(h[k]);
        A[0]  = ffma2(whhr[k*8+0], hs, A[0]);
        A[1]  = ffma2(whhr[k*8+1], hs, A[1]);
        A[2]  = ffma2(whhr[k*8+2], hs, A[2]);
        A[3]  = ffma2(whhr[k*8+3], hs, A[3]);
        A[4]  = ffma2(whhr[k*8+4], hs, A[4]);
        Hn[0] = ffma2(whhr[k*8+5], hs, Hn[0]);
        Hn[1] = ffma2(whhr[k*8+6], hs, Hn[1]);
        Hn[2] = ffma2(whhr[k*8+7], hs, Hn[2]);
    }
    float gn[6], hn[6];
#pragma unroll
    for (int p = 0; p < 3; ++p) {
        float2 a = unpack2(Gn[p]); gn[2*p] = a.x; gn[2*p+1] = a.y;
        float2 c = unpack2(Hn[p]); hn[2*p] = c.x; hn[2*p+1] = c.y;
    }
#pragma unroll
    for (int u = 0; u < 5; ++u) {
        float2 rz = unpack2(A[u]);                   // pre-scaled by 0.5
        float r  = fmaf(0.5f, tanhfast(rz.x), 0.5f);
        float z  = fmaf(0.5f, tanhfast(rz.y), 0.5f);
        float nn = tanhfast(fmaf(r, hn[u], gn[u]));
        h[u] = fmaf(z, h[u] - nn, nn);
    }
}

// fp16 triplet -> 10 floats (fwd 0..4, bwd 5..9)
__device__ __forceinline__ void cvt_in(u64 ra, u64 rb, u32 rc, float* xin)
{
    H4 a, b; H2 c; a.u = ra; b.u = rb; c.u = rc;
    float2 p0 = __half22float2(a.h[0]);
    float2 p1 = __half22float2(a.h[1]);
    float2 p2 = __half22float2(b.h[0]);
    float2 p3 = __half22float2(b.h[1]);
    float2 p4 = __half22float2(c.h);
    xin[0]=p0.x; xin[1]=p0.y; xin[2]=p1.x; xin[3]=p1.y; xin[4]=p2.x;
    xin[5]=p2.y; xin[6]=p3.x; xin[7]=p3.y; xin[8]=p4.x; xin[9]=p4.y;
}

// smem activation buffer: [T][3][BLOCK] parts (u64,u64,u32) fp16-packed
#define BUFA(t) bufA[(t)*BLOCK + tid]
#define BUFB(t) bufB[(t)*BLOCK + tid]
#define BUFC(t) bufC[(t)*BLOCK + tid]

__global__ void __launch_bounds__(BLOCK, 4)
gru_kernel(const float* __restrict__ x,
           const float* __restrict__ wih0, const float* __restrict__ whh0,
           const float* __restrict__ bih0, const float* __restrict__ bhh0,
           const float* __restrict__ wihU, const float* __restrict__ whhU,
           const float* __restrict__ bihU, const float* __restrict__ bhhU,
           float* __restrict__ out)
{
    extern __shared__ float smem[];
    float* sw   = smem;                                   // [2432]
    u64*   bufA = (u64*)(smem + WTOT);                    // [T*BLOCK] (f0..f3)
    u64*   bufB = bufA + TSTEPS*BLOCK;                    // [T*BLOCK] (f4,b0,b1,b2)
    u32*   bufC = (u32*)(bufB + TSTEPS*BLOCK);            // [T*BLOCK] (b3,b4)
    const int tid = threadIdx.x;

    // ---- cooperative weight prep: transpose to slot layout, pre-scale, merge biases ----
    for (int c = 0; c < 10; ++c) {
        int l = c >> 1, d = c & 1;
        int D = l ? 10 : 1;
        float* w = sw + comboOff(c);
        for (int i = tid; i < 16*D; i += BLOCK) {           // wihT[k][slot]
            int k = i >> 4, s = i & 15;
            float v = 0.f;
            if (s < 15) {
                int  j  = (s < 10) ? ((s & 1)*5 + (s >> 1)) : s;
                float sc = (s < 10) ? 0.5f : 1.0f;
                v = sc * (l == 0 ? wih0[d*15 + j]
                                 : wihU[(((l-1)*2 + d)*15 + j)*10 + k]);
            }
            w[i] = v;
        }
        float* wh = w + 16*D;
        for (int i = tid; i < 80; i += BLOCK) {             // whhT[k][slot]
            int k = i >> 4, s = i & 15;
            float v = 0.f;
            if (s < 15) {
                int  j  = (s < 10) ? ((s & 1)*5 + (s >> 1)) : s;
                float sc = (s < 10) ? 0.5f : 1.0f;
                v = sc * (l == 0 ? whh0[(d*15 + j)*5 + k]
                                 : whhU[(((l-1)*2 + d)*15 + j)*5 + k]);
            }
            wh[i] = v;
        }
        float* bg = wh + 80;                                // gi-side bias
        for (int s = tid; s < 16; s += BLOCK) {
            float v = 0.f;
            if (s < 15) {
                int  j  = (s < 10) ? ((s & 1)*5 + (s >> 1)) : s;
                float sc = (s < 10) ? 0.5f : 1.0f;
                float bi = l == 0 ? bih0[d*15 + j] : bihU[((l-1)*2 + d)*15 + j];
                float bh = l == 0 ? bhh0[d*15 + j] : bhhU[((l-1)*2 + d)*15 + j];
                v = sc * (s < 10 ? (bi + bh) : bi);
            }
            bg[s] = v;
        }
        float* bh2 = bg + 16;                               // gh-side n bias
        for (int s = tid; s < 16; s += BLOCK) {
            float v = 0.f;
            if (s >= 10 && s < 15)
                v = l == 0 ? bhh0[d*15 + s] : bhhU[((l-1)*2 + d)*15 + s];
            bh2[s] = v;
        }
    }
    __syncthreads();
    // buffer slots are thread-private from here on; no further syncs needed

    const int b = blockIdx.x * BLOCK + tid;
    const float* xrow = x + (size_t)b * TSTEPS;

    u64 whhr[40], bA[5], bGn[3], bHn[3];
    float h[5];
    u64 fscrA[TSTEPS];        // local: (f0..f3) fp16
    u32 fscrC[TSTEPS];        // local: (f4,pad) fp16

    // ===== layer 0 (D=1): fwd -> fscr, bwd -> merged write to smem buf =====
    {
        const float* w = sw + comboOff(0);
        load_dir(w, 1, whhr, bA, bGn, bHn);
        const float4* wih4 = (const float4*)w;
#pragma unroll
        for (int u = 0; u < 5; ++u) h[u] = 0.f;
#pragma unroll 2
        for (int t = 0; t < TSTEPS; ++t) {
            float xin[1] = { xrow[t] };
            gru_step<1>(wih4, whhr, bA, bGn, bHn, xin, h);
            fscrA[t] = h4pack(__floats2half2_rn(h[0], h[1]), __floats2half2_rn(h[2], h[3]));
            fscrC[t] = h2pack(h[4], 0.f);
        }
    }
    {
        const float* w = sw + comboOff(1);
        load_dir(w, 1, whhr, bA, bGn, bHn);
        const float4* wih4 = (const float4*)w;
#pragma unroll
        for (int u = 0; u < 5; ++u) h[u] = 0.f;
#pragma unroll 2
        for (int tt = 0; tt < TSTEPS; ++tt) {
            int t = TSTEPS-1-tt;
            u64 fa = fscrA[t]; H2 fc; fc.u = fscrC[t];     // early load (cover latency)
            float xin[1] = { xrow[t] };
            gru_step<1>(wih4, whhr, bA, bGn, bHn, xin, h);
            __half2 d0 = __floats2half2_rn(h[0], h[1]);
            __half2 d1 = __floats2half2_rn(h[2], h[3]);
            __half2 d2 = __floats2half2_rn(h[4], 0.f);
            BUFA(t) = fa;
            BUFB(t) = h4pack(__halves2half2(__low2half(fc.h), __low2half(d0)),
                             __halves2half2(__high2half(d0), __low2half(d1)));
            H2 oc; oc.h = __halves2half2(__high2half(d1), __low2half(d2));
            BUFC(t) = oc.u;
        }
    }

    // ===== layers 1..3: fwd stages into fscr, bwd overwrites smem buf in place =====
#pragma unroll 1
    for (int l = 1; l < 4; ++l) {
        {   // fwd
            const float* w = sw + comboOff(2*l);
            load_dir(w, 10, whhr, bA, bGn, bHn);
            const float4* wih4 = (const float4*)w;
#pragma unroll
            for (int u = 0; u < 5; ++u) h[u] = 0.f;
#pragma unroll 2
            for (int t = 0; t < TSTEPS; ++t) {
                float xin[10];
                cvt_in(BUFA(t), BUFB(t), BUFC(t), xin);
                gru_step<10>(wih4, whhr, bA, bGn, bHn, xin, h);
                fscrA[t] = h4pack(__floats2half2_rn(h[0], h[1]), __floats2half2_rn(h[2], h[3]));
                fscrC[t] = h2pack(h[4], 0.f);
            }
        }
        {   // bwd; fscr loaded at top of step (~full step of latency cover)
            const float* w = sw + comboOff(2*l+1);
            load_dir(w, 10, whhr, bA, bGn, bHn);
            const float4* wih4 = (const float4*)w;
#pragma unroll
            for (int u = 0; u < 5; ++u) h[u] = 0.f;
#pragma unroll 2
            for (int tt = 0; tt < TSTEPS; ++tt) {
                int t = TSTEPS-1-tt;
                u64 fa = fscrA[t]; H2 fc; fc.u = fscrC[t];
                float xin[10];
                cvt_in(BUFA(t), BUFB(t), BUFC(t), xin);
                gru_step<10>(wih4, whhr, bA, bGn, bHn, xin, h);
                __half2 d0 = __floats2half2_rn(h[0], h[1]);
                __half2 d1 = __floats2half2_rn(h[2], h[3]);
                __half2 d2 = __floats2half2_rn(h[4], 0.f);
                BUFA(t) = fa;
                BUFB(t) = h4pack(__halves2half2(__low2half(fc.h), __low2half(d0)),
                                 __halves2half2(__high2half(d0), __low2half(d1)));
                H2 oc; oc.h = __halves2half2(__high2half(d1), __low2half(d2));
                BUFC(t) = oc.u;
            }
        }
    }

    // ===== layer 4: fwd full (keep final h only); bwd = ONE step at t=T-1 =====
    float hf[5];
    {
        const float* w = sw + comboOff(8);
        load_dir(w, 10, whhr, bA, bGn, bHn);
        const float4* wih4 = (const float4*)w;
#pragma unroll
        for (int u = 0; u < 5; ++u) h[u] = 0.f;
#pragma unroll 2
        for (int t = 0; t < TSTEPS; ++t) {
            float xin[10];
            cvt_in(BUFA(t), BUFB(t), BUFC(t), xin);
            gru_step<10>(wih4, whhr, bA, bGn, bHn, xin, h);
        }
#pragma unroll
        for (int u = 0; u < 5; ++u) hf[u] = h[u];
    }
    {
        const float* w = sw + comboOff(9);
        load_dir(w, 10, whhr, bA, bGn, bHn);
        const float4* wih4 = (const float4*)w;
#pragma unroll
        for (int u = 0; u < 5; ++u) h[u] = 0.f;
        float xin[10];
        int t = TSTEPS-1;
        cvt_in(BUFA(t), BUFB(t), BUFC(t), xin);
        gru_step<10>(wih4, whhr, bA, bGn, bHn, xin, h);
    }

    float2* o2 = (float2*)(out + (size_t)b*10);
    o2[0] = make_float2(hf[0], hf[1]);
    o2[1] = make_float2(hf[2], hf[3]);
    o2[2] = make_float2(hf[4], h[0]);
    o2[3] = make_float2(h[1],  h[2]);
    o2[4] = make_float2(h[3],  h[4]);
}

extern "C" void kernel_launch(void* const* d_in, const int* in_sizes, int n_in,
                              void* d_out, int out_size)
{
    (void)in_sizes; (void)n_in; (void)out_size;
    // 9728 (weights) + 30*64*(8+8+4) = 48128 B -> 4 blocks/SM (R5 config)
    const size_t smem = (size_t)WTOT*4 + (size_t)TSTEPS*BLOCK*(8+8+4);
    cudaFuncSetAttribute(gru_kernel, cudaFuncAttributeMaxDynamicSharedMemorySize, (int)smem);
    gru_kernel<<<NBATCH/BLOCK, BLOCK, smem>>>(
        (const float*)d_in[0],
        (const float*)d_in[1], (const float*)d_in[2],
        (const float*)d_in[3], (const float*)d_in[4],
        (const float*)d_in[5], (const float*)d_in[6],
        (const float*)d_in[7], (const float*)d_in[8],
        (float*)d_out);
}

// round 12
// speedup vs baseline: 2.0958x; 1.0707x over previous
#include <cuda_runtime.h>
#include <cuda_fp16.h>

#define TSTEPS 30
#define BLOCK  64
#define NBATCH 262144

constexpr int WTOT = 2432;                       // prepped weight floats in smem

typedef unsigned long long u64;
typedef unsigned int       u32;

// ---------- packed fp32x2 helpers (sm_103a FFMA2 path) ----------
__device__ __forceinline__ u64 ffma2(u64 a, u64 b, u64 c) {
    u64 d; asm("fma.rn.f32x2 %0, %1, %2, %3;" : "=l"(d) : "l"(a), "l"(b), "l"(c)); return d;
}
__device__ __forceinline__ u64 splat2(float v) {
    u64 d; asm("mov.b64 %0, {%1, %1};" : "=l"(d) : "f"(v)); return d;
}
__device__ __forceinline__ u64 pack2(float x, float y) {
    u64 d; asm("mov.b64 %0, {%1, %2};" : "=l"(d) : "f"(x), "f"(y)); return d;
}
__device__ __forceinline__ float2 unpack2(u64 v) {
    float2 r; asm("mov.b64 {%0, %1}, %2;" : "=f"(r.x), "=f"(r.y) : "l"(v)); return r;
}
__device__ __forceinline__ float tanhfast(float x){ float r; asm("tanh.approx.f32 %0, %1;" : "=f"(r) : "f"(x)); return r; }

__device__ __forceinline__ int comboOff(int c){ return c < 2 ? c*128 : 256 + (c-2)*272; }

union H4 { u64 u; u32 w[2]; __half2 h[2]; };
union H2 { u32 u; __half2 h; };
__device__ __forceinline__ u64 h4pack(__half2 a, __half2 b){ H4 t; t.h[0]=a; t.h[1]=b; return t.u; }
__device__ __forceinline__ u32 h2pack(float x, float y){ H2 t; t.h = __floats2half2_rn(x,y); return t.u; }

// Slot order (rz-merged): s=2u+g, g in {r,z}, unit u (s<10); s=10..14 n-gate; s=15 pad.
// r/z rows scaled 0.5 (gi+gh merged): sig(v)=0.5+0.5*tanh(v/2); n rows unscaled.

// ---------- per-direction constants: ONLY W_hh (5x16) in registers ----------
__device__ __forceinline__ void load_whh(const float* wbase, int D, u64* whhr)
{
    const float4* wh4 = (const float4*)(wbase + 16*D);
#pragma unroll
    for (int k = 0; k < 5; ++k)
#pragma unroll
        for (int qq = 0; qq < 4; ++qq) {
            float4 a = wh4[k*4+qq];
            whhr[k*8+qq*2+0] = pack2(a.x, a.y);
            whhr[k*8+qq*2+1] = pack2(a.z, a.w);
        }
}

// ---------- gi phase: x-side GEMV + bias init (independent of h) ----------
template<int D>
__device__ __forceinline__ void compute_gi(const float* __restrict__ wbase,
                                           const float* xin, u64* A, u64* Gn)
{
    const float4* wih4 = (const float4*)wbase;
    const float4* bg4  = (const float4*)(wbase + 16*D + 80);
    float4 c0 = bg4[0], c1 = bg4[1], c2 = bg4[2], c3 = bg4[3];
    A[0] = pack2(c0.x,c0.y); A[1] = pack2(c0.z,c0.w);
    A[2] = pack2(c1.x,c1.y); A[3] = pack2(c1.z,c1.w);
    A[4] = pack2(c2.x,c2.y);
    Gn[0] = pack2(c2.z,c2.w); Gn[1] = pack2(c3.x,c3.y); Gn[2] = pack2(c3.z,c3.w);
#pragma unroll
    for (int k = 0; k < D; ++k) {
        u64 xs = splat2(xin[k]);
        float4 w0 = wih4[k*4+0], w1 = wih4[k*4+1], w2 = wih4[k*4+2], w3 = wih4[k*4+3];
        A[0]  = ffma2(pack2(w0.x,w0.y), xs, A[0]);
        A[1]  = ffma2(pack2(w0.z,w0.w), xs, A[1]);
        A[2]  = ffma2(pack2(w1.x,w1.y), xs, A[2]);
        A[3]  = ffma2(pack2(w1.z,w1.w), xs, A[3]);
        A[4]  = ffma2(pack2(w2.x,w2.y), xs, A[4]);
        Gn[0] = ffma2(pack2(w2.z,w2.w), xs, Gn[0]);
        Gn[1] = ffma2(pack2(w3.x,w3.y), xs, Gn[1]);
        Gn[2] = ffma2(pack2(w3.z,w3.w), xs, Gn[2]);
    }
}

// ---------- h phase: whh GEMV (register-resident weights) + nonlinearity ----------
template<int D>
__device__ __forceinline__ void gru_tail(const float* __restrict__ wbase,
                                         const u64* whhr,
                                         const u64* Ain, const u64* GnIn, float* h)
{
    const float4* bh4 = (const float4*)(wbase + 16*D + 96);
    u64 A[5], Hn[3];
#pragma unroll
    for (int p = 0; p < 5; ++p) A[p] = Ain[p];
    {
        float4 d2 = bh4[2], d3 = bh4[3];
        Hn[0] = pack2(d2.z,d2.w); Hn[1] = pack2(d3.x,d3.y); Hn[2] = pack2(d3.z,d3.w);
    }
#pragma unroll
    for (int k = 0; k < 5; ++k) {
        u64 hs = splat2(h[k]);
        A[0]  = ffma2(whhr[k*8+0], hs, A[0]);
        A[1]  = ffma2(whhr[k*8+1], hs, A[1]);
        A[2]  = ffma2(whhr[k*8+2], hs, A[2]);
        A[3]  = ffma2(whhr[k*8+3], hs, A[3]);
        A[4]  = ffma2(whhr[k*8+4], hs, A[4]);
        Hn[0] = ffma2(whhr[k*8+5], hs, Hn[0]);
        Hn[1] = ffma2(whhr[k*8+6], hs, Hn[1]);
        Hn[2] = ffma2(whhr[k*8+7], hs, Hn[2]);
    }
    float gn[6], hn[6];
#pragma unroll
    for (int p = 0; p < 3; ++p) {
        float2 a = unpack2(GnIn[p]); gn[2*p] = a.x; gn[2*p+1] = a.y;
        float2 c = unpack2(Hn[p]);   hn[2*p] = c.x; hn[2*p+1] = c.y;
    }
#pragma unroll
    for (int u = 0; u < 5; ++u) {
        float2 rz = unpack2(A[u]);                   // pre-scaled by 0.5
        float r  = fmaf(0.5f, tanhfast(rz.x), 0.5f);
        float z  = fmaf(0.5f, tanhfast(rz.y), 0.5f);
        float nn = tanhfast(fmaf(r, hn[u], gn[u]));
        h[u] = fmaf(z, h[u] - nn, nn);
    }
}

// fp16 triplet -> 10 floats (fwd 0..4, bwd 5..9)
__device__ __forceinline__ void cvt_in(u64 ra, u64 rb, u32 rc, float* xin)
{
    H4 a, b; H2 c; a.u = ra; b.u = rb; c.u = rc;
    float2 p0 = __half22float2(a.h[0]);
    float2 p1 = __half22float2(a.h[1]);
    float2 p2 = __half22float2(b.h[0]);
    float2 p3 = __half22float2(b.h[1]);
    float2 p4 = __half22float2(c.h);
    xin[0]=p0.x; xin[1]=p0.y; xin[2]=p1.x; xin[3]=p1.y; xin[4]=p2.x;
    xin[5]=p2.y; xin[6]=p3.x; xin[7]=p3.y; xin[8]=p4.x; xin[9]=p4.y;
}

#define BUFA(t) bufA[(t)*BLOCK + tid]
#define BUFB(t) bufB[(t)*BLOCK + tid]
#define BUFC(t) bufC[(t)*BLOCK + tid]

// merged entry write: fwd-staged (fa,fc) + bwd h
#define WRITE_ENTRY(t, fa, fcu) do {                                             \
    __half2 d0 = __floats2half2_rn(h[0], h[1]);                                  \
    __half2 d1 = __floats2half2_rn(h[2], h[3]);                                  \
    __half2 d2 = __floats2half2_rn(h[4], 0.f);                                   \
    H2 fc_; fc_.u = (fcu);                                                       \
    BUFA(t) = (fa);                                                              \
    BUFB(t) = h4pack(__halves2half2(__low2half(fc_.h), __low2half(d0)),          \
                     __halves2half2(__high2half(d0), __low2half(d1)));           \
    H2 oc_; oc_.h = __halves2half2(__high2half(d1), __low2half(d2));             \
    BUFC(t) = oc_.u;                                                             \
} while (0)

__global__ void __launch_bounds__(BLOCK, 4)
gru_kernel(const float* __restrict__ x,
           const float* __restrict__ wih0, const float* __restrict__ whh0,
           const float* __restrict__ bih0, const float* __restrict__ bhh0,
           const float* __restrict__ wihU, const float* __restrict__ whhU,
           const float* __restrict__ bihU, const float* __restrict__ bhhU,
           float* __restrict__ out)
{
    extern __shared__ float smem[];
    float* sw   = smem;                                   // [2432]
    u64*   bufA = (u64*)(smem + WTOT);                    // [T*BLOCK] (f0..f3)
    u64*   bufB = bufA + TSTEPS*BLOCK;                    // [T*BLOCK] (f4,b0,b1,b2)
    u32*   bufC = (u32*)(bufB + TSTEPS*BLOCK);            // [T*BLOCK] (b3,b4)
    const int tid = threadIdx.x;

    // ---- cooperative weight prep: transpose to slot layout, pre-scale, merge biases ----
    for (int c = 0; c < 10; ++c) {
        int l = c >> 1, d = c & 1;
        int D = l ? 10 : 1;
        float* w = sw + comboOff(c);
        for (int i = tid; i < 16*D; i += BLOCK) {           // wihT[k][slot]
            int k = i >> 4, s = i & 15;
            float v = 0.f;
            if (s < 15) {
                int  j  = (s < 10) ? ((s & 1)*5 + (s >> 1)) : s;
                float sc = (s < 10) ? 0.5f : 1.0f;
                v = sc * (l == 0 ? wih0[d*15 + j]
                                 : wihU[(((l-1)*2 + d)*15 + j)*10 + k]);
            }
            w[i] = v;
        }
        float* wh = w + 16*D;
        for (int i = tid; i < 80; i += BLOCK) {             // whhT[k][slot]
            int k = i >> 4, s = i & 15;
            float v = 0.f;
            if (s < 15) {
                int  j  = (s < 10) ? ((s & 1)*5 + (s >> 1)) : s;
                float sc = (s < 10) ? 0.5f : 1.0f;
                v = sc * (l == 0 ? whh0[(d*15 + j)*5 + k]
                                 : whhU[(((l-1)*2 + d)*15 + j)*5 + k]);
            }
            wh[i] = v;
        }
        float* bg = wh + 80;                                // gi-side bias
        for (int s = tid; s < 16; s += BLOCK) {
            float v = 0.f;
            if (s < 15) {
                int  j  = (s < 10) ? ((s & 1)*5 + (s >> 1)) : s;
                float sc = (s < 10) ? 0.5f : 1.0f;
                float bi = l == 0 ? bih0[d*15 + j] : bihU[((l-1)*2 + d)*15 + j];
                float bh = l == 0 ? bhh0[d*15 + j] : bhhU[((l-1)*2 + d)*15 + j];
                v = sc * (s < 10 ? (bi + bh) : bi);
            }
            bg[s] = v;
        }
        float* bh2 = bg + 16;                               // gh-side n bias
        for (int s = tid; s < 16; s += BLOCK) {
            float v = 0.f;
            if (s >= 10 && s < 15)
                v = l == 0 ? bhh0[d*15 + s] : bhhU[((l-1)*2 + d)*15 + s];
            bh2[s] = v;
        }
    }
    __syncthreads();
    // buffer slots are thread-private from here on; no further syncs needed

    const int b = blockIdx.x * BLOCK + tid;
    const float* xrow = x + (size_t)b * TSTEPS;

    u64 whhr[40];
    float h[5];
    u64 fscrA[TSTEPS];        // local: (f0..f3) fp16
    u32 fscrC[TSTEPS];        // local: (f4,pad) fp16

    // ===== layer 0 (D=1): simple loops (cheap steps) =====
    {
        const float* w = sw + comboOff(0);
        load_whh(w, 1, whhr);
#pragma unroll
        for (int u = 0; u < 5; ++u) h[u] = 0.f;
#pragma unroll 1
        for (int t = 0; t < TSTEPS; ++t) {
            float xin[1] = { xrow[t] };
            u64 A[5], Gn[3];
            compute_gi<1>(w, xin, A, Gn);
            gru_tail<1>(w, whhr, A, Gn, h);
            fscrA[t] = h4pack(__floats2half2_rn(h[0], h[1]), __floats2half2_rn(h[2], h[3]));
            fscrC[t] = h2pack(h[4], 0.f);
        }
    }
    {
        const float* w = sw + comboOff(1);
        load_whh(w, 1, whhr);
#pragma unroll
        for (int u = 0; u < 5; ++u) h[u] = 0.f;
#pragma unroll 1
        for (int tt = 0; tt < TSTEPS; ++tt) {
            int t = TSTEPS-1-tt;
            u64 fa = fscrA[t]; u32 fc = fscrC[t];          // early load (cover latency)
            float xin[1] = { xrow[t] };
            u64 A[5], Gn[3];
            compute_gi<1>(w, xin, A, Gn);
            gru_tail<1>(w, whhr, A, Gn, h);
            WRITE_ENTRY(t, fa, fc);
        }
    }

    // ===== layers 1..3: software-pipelined gi (x-side of step t+1 overlaps tail of t) =====
#pragma unroll 1
    for (int l = 1; l < 4; ++l) {
        {   // fwd
            const float* w = sw + comboOff(2*l);
            load_whh(w, 10, whhr);
#pragma unroll
            for (int u = 0; u < 5; ++u) h[u] = 0.f;
            u64 A0[5], Gn0[3], A1[5], Gn1[3];
            {
                float xin[10];
                cvt_in(BUFA(0), BUFB(0), BUFC(0), xin);
                compute_gi<10>(w, xin, A0, Gn0);
            }
#pragma unroll 1
            for (int t = 0; t < TSTEPS; t += 2) {
                {   // step t: gi(t+1) issued alongside tail(t)
                    float xin[10];
                    cvt_in(BUFA(t+1), BUFB(t+1), BUFC(t+1), xin);
                    compute_gi<10>(w, xin, A1, Gn1);
                    gru_tail<10>(w, whhr, A0, Gn0, h);
                    fscrA[t] = h4pack(__floats2half2_rn(h[0], h[1]), __floats2half2_rn(h[2], h[3]));
                    fscrC[t] = h2pack(h[4], 0.f);
                }
                {   // step t+1: gi(t+2, clamped) alongside tail(t+1)
                    int tn = (t+2 < TSTEPS) ? t+2 : TSTEPS-1;
                    float xin[10];
                    cvt_in(BUFA(tn), BUFB(tn), BUFC(tn), xin);
                    compute_gi<10>(w, xin, A0, Gn0);
                    gru_tail<10>(w, whhr, A1, Gn1, h);
                    fscrA[t+1] = h4pack(__floats2half2_rn(h[0], h[1]), __floats2half2_rn(h[2], h[3]));
                    fscrC[t+1] = h2pack(h[4], 0.f);
                }
            }
        }
        {   // bwd (descending); reads entry t-1 before overwriting entry t
            const float* w = sw + comboOff(2*l+1);
            load_whh(w, 10, whhr);
#pragma unroll
            for (int u = 0; u < 5; ++u) h[u] = 0.f;
            u64 A0[5], Gn0[3], A1[5], Gn1[3];
            {
                float xin[10];
                cvt_in(BUFA(TSTEPS-1), BUFB(TSTEPS-1), BUFC(TSTEPS-1), xin);
                compute_gi<10>(w, xin, A0, Gn0);
            }
#pragma unroll 1
            for (int tt = 0; tt < TSTEPS; tt += 2) {
                int t = TSTEPS-1-tt;                        // t >= 1
                {   // position t
                    u64 fa = fscrA[t]; u32 fc = fscrC[t];
                    float xin[10];
                    cvt_in(BUFA(t-1), BUFB(t-1), BUFC(t-1), xin);
                    compute_gi<10>(w, xin, A1, Gn1);
                    gru_tail<10>(w, whhr, A0, Gn0, h);
                    WRITE_ENTRY(t, fa, fc);
                }
                {   // position t-1
                    int tn = (t-2 >= 0) ? t-2 : 0;
                    u64 fa = fscrA[t-1]; u32 fc = fscrC[t-1];
                    float xin[10];
                    cvt_in(BUFA(tn), BUFB(tn), BUFC(tn), xin);
                    compute_gi<10>(w, xin, A0, Gn0);
                    gru_tail<10>(w, whhr, A1, Gn1, h);
                    WRITE_ENTRY(t-1, fa, fc);
                }
            }
        }
    }

    // ===== layer 4: fwd full (pipelined, keep final h only); bwd = ONE step =====
    float hf[5];
    {
        const float* w = sw + comboOff(8);
        load_whh(w, 10, whhr);
#pragma unroll
        for (int u = 0; u < 5; ++u) h[u] = 0.f;
        u64 A0[5], Gn0[3], A1[5], Gn1[3];
        {
            float xin[10];
            cvt_in(BUFA(0), BUFB(0), BUFC(0), xin);
            compute_gi<10>(w, xin, A0, Gn0);
        }
#pragma unroll 1
        for (int t = 0; t < TSTEPS; t += 2) {
            {
                float xin[10];
                cvt_in(BUFA(t+1), BUFB(t+1), BUFC(t+1), xin);
                compute_gi<10>(w, xin, A1, Gn1);
                gru_tail<10>(w, whhr, A0, Gn0, h);
            }
            {
                int tn = (t+2 < TSTEPS) ? t+2 : TSTEPS-1;
                float xin[10];
                cvt_in(BUFA(tn), BUFB(tn), BUFC(tn), xin);
                compute_gi<10>(w, xin, A0, Gn0);
                gru_tail<10>(w, whhr, A1, Gn1, h);
            }
        }
#pragma unroll
        for (int u = 0; u < 5; ++u) hf[u] = h[u];
    }
    {
        const float* w = sw + comboOff(9);
        load_whh(w, 10, whhr);
#pragma unroll
        for (int u = 0; u < 5; ++u) h[u] = 0.f;
        float xin[10];
        int t = TSTEPS-1;
        cvt_in(BUFA(t), BUFB(t), BUFC(t), xin);
        u64 A[5], Gn[3];
        compute_gi<10>(w, xin, A, Gn);
        gru_tail<10>(w, whhr, A, Gn, h);
    }

    float2* o2 = (float2*)(out + (size_t)b*10);
    o2[0] = make_float2(hf[0], hf[1]);
    o2[1] = make_float2(hf[2], hf[3]);
    o2[2] = make_float2(hf[4], h[0]);
    o2[3] = make_float2(h[1],  h[2]);
    o2[4] = make_float2(h[3],  h[4]);
}

extern "C" void kernel_launch(void* const* d_in, const int* in_sizes, int n_in,
                              void* d_out, int out_size)
{
    (void)in_sizes; (void)n_in; (void)out_size;
    // 9728 (weights) + 30*64*(8+8+4) = 48128 B -> 4 blocks/SM (R5 config)
    const size_t smem = (size_t)WTOT*4 + (size_t)TSTEPS*BLOCK*(8+8+4);
    cudaFuncSetAttribute(gru_kernel, cudaFuncAttributeMaxDynamicSharedMemorySize, (int)smem);
    gru_kernel<<<NBATCH/BLOCK, BLOCK, smem>>>(
        (const float*)d_in[0],
        (const float*)d_in[1], (const float*)d_in[2],
        (const float*)d_in[3], (const float*)d_in[4],
        (const float*)d_in[5], (const float*)d_in[6],
        (const float*)d_in[7], (const float*)d_in[8],
        (float*)d_out);
}

// round 13
// speedup vs baseline: 2.0958x; 1.0000x over previous
#include <cuda_runtime.h>
#include <cuda_fp16.h>

#define TSTEPS 30
#define BLOCK  64
#define NBATCH 262144

constexpr int WTOT = 2432;                       // prepped weight floats in smem

typedef unsigned long long u64;
typedef unsigned int       u32;

// ---------- packed fp32x2 helpers (sm_103a FFMA2 path) ----------
__device__ __forceinline__ u64 ffma2(u64 a, u64 b, u64 c) {
    u64 d; asm("fma.rn.f32x2 %0, %1, %2, %3;" : "=l"(d) : "l"(a), "l"(b), "l"(c)); return d;
}
__device__ __forceinline__ u64 splat2(float v) {
    u64 d; asm("mov.b64 %0, {%1, %1};" : "=l"(d) : "f"(v)); return d;
}
__device__ __forceinline__ u64 pack2(float x, float y) {
    u64 d; asm("mov.b64 %0, {%1, %2};" : "=l"(d) : "f"(x), "f"(y)); return d;
}
__device__ __forceinline__ float2 unpack2(u64 v) {
    float2 r; asm("mov.b64 {%0, %1}, %2;" : "=f"(r.x), "=f"(r.y) : "l"(v)); return r;
}
__device__ __forceinline__ float tanhfast(float x){ float r; asm("tanh.approx.f32 %0, %1;" : "=f"(r) : "f"(x)); return r; }

__device__ __forceinline__ int comboOff(int c){ return c < 2 ? c*128 : 256 + (c-2)*272; }

union H4 { u64 u; u32 w[2]; __half2 h[2]; };
union H2 { u32 u; __half2 h; };
__device__ __forceinline__ u64 h4pack(__half2 a, __half2 b){ H4 t; t.h[0]=a; t.h[1]=b; return t.u; }
__device__ __forceinline__ u32 h2pack(float x, float y){ H2 t; t.h = __floats2half2_rn(x,y); return t.u; }

// Slot order (rz-merged): s=2u+g, g in {r,z}, unit u (s<10); s=10..14 n-gate; s=15 pad.
// r/z rows scaled 0.5 (gi+gh merged): sig(v)=0.5+0.5*tanh(v/2); n rows unscaled.

// ---------- per-direction constants: ONLY W_hh (5x16) in registers ----------
__device__ __forceinline__ void load_whh(const float* wbase, int D, u64* whhr)
{
    const float4* wh4 = (const float4*)(wbase + 16*D);
#pragma unroll
    for (int k = 0; k < 5; ++k)
#pragma unroll
        for (int qq = 0; qq < 4; ++qq) {
            float4 a = wh4[k*4+qq];
            whhr[k*8+qq*2+0] = pack2(a.x, a.y);
            whhr[k*8+qq*2+1] = pack2(a.z, a.w);
        }
}

// ---------- gi phase: x-side GEMV + bias init (independent of h) ----------
template<int D>
__device__ __forceinline__ void compute_gi(const float* __restrict__ wbase,
                                           const float* xin, u64* A, u64* Gn)
{
    const float4* wih4 = (const float4*)wbase;
    const float4* bg4  = (const float4*)(wbase + 16*D + 80);
    float4 c0 = bg4[0], c1 = bg4[1], c2 = bg4[2], c3 = bg4[3];
    A[0] = pack2(c0.x,c0.y); A[1] = pack2(c0.z,c0.w);
    A[2] = pack2(c1.x,c1.y); A[3] = pack2(c1.z,c1.w);
    A[4] = pack2(c2.x,c2.y);
    Gn[0] = pack2(c2.z,c2.w); Gn[1] = pack2(c3.x,c3.y); Gn[2] = pack2(c3.z,c3.w);
#pragma unroll
    for (int k = 0; k < D; ++k) {
        u64 xs = splat2(xin[k]);
        float4 w0 = wih4[k*4+0], w1 = wih4[k*4+1], w2 = wih4[k*4+2], w3 = wih4[k*4+3];
        A[0]  = ffma2(pack2(w0.x,w0.y), xs, A[0]);
        A[1]  = ffma2(pack2(w0.z,w0.w), xs, A[1]);
        A[2]  = ffma2(pack2(w1.x,w1.y), xs, A[2]);
        A[3]  = ffma2(pack2(w1.z,w1.w), xs, A[3]);
        A[4]  = ffma2(pack2(w2.x,w2.y), xs, A[4]);
        Gn[0] = ffma2(pack2(w2.z,w2.w), xs, Gn[0]);
        Gn[1] = ffma2(pack2(w3.x,w3.y), xs, Gn[1]);
        Gn[2] = ffma2(pack2(w3.z,w3.w), xs, Gn[2]);
    }
}

// ---------- h phase: whh GEMV (register-resident weights) + nonlinearity ----------
template<int D>
__device__ __forceinline__ void gru_tail(const float* __restrict__ wbase,
                                         const u64* whhr,
                                         const u64* Ain, const u64* GnIn, float* h)
{
    const float4* bh4 = (const float4*)(wbase + 16*D + 96);
    u64 A[5], Hn[3];
#pragma unroll
    for (int p = 0; p < 5; ++p) A[p] = Ain[p];
    {
        float4 d2 = bh4[2], d3 = bh4[3];
        Hn[0] = pack2(d2.z,d2.w); Hn[1] = pack2(d3.x,d3.y); Hn[2] = pack2(d3.z,d3.w);
    }
#pragma unroll
    for (int k = 0; k < 5; ++k) {
        u64 hs = splat2(h[k]);
        A[0]  = ffma2(whhr[k*8+0], hs, A[0]);
        A[1]  = ffma2(whhr[k*8+1], hs, A[1]);
        A[2]  = ffma2(whhr[k*8+2], hs, A[2]);
        A[3]  = ffma2(whhr[k*8+3], hs, A[3]);
        A[4]  = ffma2(whhr[k*8+4], hs, A[4]);
        Hn[0] = ffma2(whhr[k*8+5], hs, Hn[0]);
        Hn[1] = ffma2(whhr[k*8+6], hs, Hn[1]);
        Hn[2] = ffma2(whhr[k*8+7], hs, Hn[2]);
    }
    float gn[6], hn[6];
#pragma unroll
    for (int p = 0; p < 3; ++p) {
        float2 a = unpack2(GnIn[p]); gn[2*p] = a.x; gn[2*p+1] = a.y;
        float2 c = unpack2(Hn[p]);   hn[2*p] = c.x; hn[2*p+1] = c.y;
    }
#pragma unroll
    for (int u = 0; u < 5; ++u) {
        float2 rz = unpack2(A[u]);                   // pre-scaled by 0.5
        float r  = fmaf(0.5f, tanhfast(rz.x), 0.5f);
        float z  = fmaf(0.5f, tanhfast(rz.y), 0.5f);
        float nn = tanhfast(fmaf(r, hn[u], gn[u]));
        h[u] = fmaf(z, h[u] - nn, nn);
    }
}

// fp16 triplet -> 10 floats (fwd 0..4, bwd 5..9)
__device__ __forceinline__ void cvt_in(u64 ra, u64 rb, u32 rc, float* xin)
{
    H4 a, b; H2 c; a.u = ra; b.u = rb; c.u = rc;
    float2 p0 = __half22float2(a.h[0]);
    float2 p1 = __half22float2(a.h[1]);
    float2 p2 = __half22float2(b.h[0]);
    float2 p3 = __half22float2(b.h[1]);
    float2 p4 = __half22float2(c.h);
    xin[0]=p0.x; xin[1]=p0.y; xin[2]=p1.x; xin[3]=p1.y; xin[4]=p2.x;
    xin[5]=p2.y; xin[6]=p3.x; xin[7]=p3.y; xin[8]=p4.x; xin[9]=p4.y;
}

#define BUFA(t) bufA[(t)*BLOCK + tid]
#define BUFB(t) bufB[(t)*BLOCK + tid]
#define BUFC(t) bufC[(t)*BLOCK + tid]

// merged entry write: fwd-staged (fa,fc) + bwd h
#define WRITE_ENTRY(t, fa, fcu) do {                                             \
    __half2 d0 = __floats2half2_rn(h[0], h[1]);                                  \
    __half2 d1 = __floats2half2_rn(h[2], h[3]);                                  \
    __half2 d2 = __floats2half2_rn(h[4], 0.f);                                   \
    H2 fc_; fc_.u = (fcu);                                                       \
    BUFA(t) = (fa);                                                              \
    BUFB(t) = h4pack(__halves2half2(__low2half(fc_.h), __low2half(d0)),          \
                     __halves2half2(__high2half(d0), __low2half(d1)));           \
    H2 oc_; oc_.h = __halves2half2(__high2half(d1), __low2half(d2));             \
    BUFC(t) = oc_.u;                                                             \
} while (0)

__global__ void __launch_bounds__(BLOCK, 4)
gru_kernel(const float* __restrict__ x,
           const float* __restrict__ wih0, const float* __restrict__ whh0,
           const float* __restrict__ bih0, const float* __restrict__ bhh0,
           const float* __restrict__ wihU, const float* __restrict__ whhU,
           const float* __restrict__ bihU, const float* __restrict__ bhhU,
           float* __restrict__ out)
{
    extern __shared__ float smem[];
    float* sw   = smem;                                   // [2432]
    u64*   bufA = (u64*)(smem + WTOT);                    // [T*BLOCK] (f0..f3)
    u64*   bufB = bufA + TSTEPS*BLOCK;                    // [T*BLOCK] (f4,b0,b1,b2)
    u32*   bufC = (u32*)(bufB + TSTEPS*BLOCK);            // [T*BLOCK] (b3,b4)
    const int tid = threadIdx.x;

    // ---- cooperative weight prep: transpose to slot layout, pre-scale, merge biases ----
    for (int c = 0; c < 10; ++c) {
        int l = c >> 1, d = c & 1;
        int D = l ? 10 : 1;
        float* w = sw + comboOff(c);
        for (int i = tid; i < 16*D; i += BLOCK) {           // wihT[k][slot]
            int k = i >> 4, s = i & 15;
            float v = 0.f;
            if (s < 15) {
                int  j  = (s < 10) ? ((s & 1)*5 + (s >> 1)) : s;
                float sc = (s < 10) ? 0.5f : 1.0f;
                v = sc * (l == 0 ? wih0[d*15 + j]
                                 : wihU[(((l-1)*2 + d)*15 + j)*10 + k]);
            }
            w[i] = v;
        }
        float* wh = w + 16*D;
        for (int i = tid; i < 80; i += BLOCK) {             // whhT[k][slot]
            int k = i >> 4, s = i & 15;
            float v = 0.f;
            if (s < 15) {
                int  j  = (s < 10) ? ((s & 1)*5 + (s >> 1)) : s;
                float sc = (s < 10) ? 0.5f : 1.0f;
                v = sc * (l == 0 ? whh0[(d*15 + j)*5 + k]
                                 : whhU[(((l-1)*2 + d)*15 + j)*5 + k]);
            }
            wh[i] = v;
        }
        float* bg = wh + 80;                                // gi-side bias
        for (int s = tid; s < 16; s += BLOCK) {
            float v = 0.f;
            if (s < 15) {
                int  j  = (s < 10) ? ((s & 1)*5 + (s >> 1)) : s;
                float sc = (s < 10) ? 0.5f : 1.0f;
                float bi = l == 0 ? bih0[d*15 + j] : bihU[((l-1)*2 + d)*15 + j];
                float bh = l == 0 ? bhh0[d*15 + j] : bhhU[((l-1)*2 + d)*15 + j];
                v = sc * (s < 10 ? (bi + bh) : bi);
            }
            bg[s] = v;
        }
        float* bh2 = bg + 16;                               // gh-side n bias
        for (int s = tid; s < 16; s += BLOCK) {
            float v = 0.f;
            if (s >= 10 && s < 15)
                v = l == 0 ? bhh0[d*15 + s] : bhhU[((l-1)*2 + d)*15 + s];
            bh2[s] = v;
        }
    }
    __syncthreads();
    // buffer slots are thread-private from here on; no further syncs needed

    const int b = blockIdx.x * BLOCK + tid;
    const float* xrow = x + (size_t)b * TSTEPS;

    u64 whhr[40];
    float h[5];
    u64 fscrA[TSTEPS];        // local: (f0..f3) fp16
    u32 fscrC[TSTEPS];        // local: (f4,pad) fp16

    // ===== layer 0 (D=1): simple loops (cheap steps) =====
    {
        const float* w = sw + comboOff(0);
        load_whh(w, 1, whhr);
#pragma unroll
        for (int u = 0; u < 5; ++u) h[u] = 0.f;
#pragma unroll 1
        for (int t = 0; t < TSTEPS; ++t) {
            float xin[1] = { xrow[t] };
            u64 A[5], Gn[3];
            compute_gi<1>(w, xin, A, Gn);
            gru_tail<1>(w, whhr, A, Gn, h);
            fscrA[t] = h4pack(__floats2half2_rn(h[0], h[1]), __floats2half2_rn(h[2], h[3]));
            fscrC[t] = h2pack(h[4], 0.f);
        }
    }
    {
        const float* w = sw + comboOff(1);
        load_whh(w, 1, whhr);
#pragma unroll
        for (int u = 0; u < 5; ++u) h[u] = 0.f;
#pragma unroll 1
        for (int tt = 0; tt < TSTEPS; ++tt) {
            int t = TSTEPS-1-tt;
            u64 fa = fscrA[t]; u32 fc = fscrC[t];          // early load (cover latency)
            float xin[1] = { xrow[t] };
            u64 A[5], Gn[3];
            compute_gi<1>(w, xin, A, Gn);
            gru_tail<1>(w, whhr, A, Gn, h);
            WRITE_ENTRY(t, fa, fc);
        }
    }

    // ===== layers 1..3: software-pipelined gi (x-side of step t+1 overlaps tail of t) =====
#pragma unroll 1
    for (int l = 1; l < 4; ++l) {
        {   // fwd
            const float* w = sw + comboOff(2*l);
            load_whh(w, 10, whhr);
#pragma unroll
            for (int u = 0; u < 5; ++u) h[u] = 0.f;
            u64 A0[5], Gn0[3], A1[5], Gn1[3];
            {
                float xin[10];
                cvt_in(BUFA(0), BUFB(0), BUFC(0), xin);
                compute_gi<10>(w, xin, A0, Gn0);
            }
#pragma unroll 1
            for (int t = 0; t < TSTEPS; t += 2) {
                {   // step t: gi(t+1) issued alongside tail(t)
                    float xin[10];
                    cvt_in(BUFA(t+1), BUFB(t+1), BUFC(t+1), xin);
                    compute_gi<10>(w, xin, A1, Gn1);
                    gru_tail<10>(w, whhr, A0, Gn0, h);
                    fscrA[t] = h4pack(__floats2half2_rn(h[0], h[1]), __floats2half2_rn(h[2], h[3]));
                    fscrC[t] = h2pack(h[4], 0.f);
                }
                {   // step t+1: gi(t+2, clamped) alongside tail(t+1)
                    int tn = (t+2 < TSTEPS) ? t+2 : TSTEPS-1;
                    float xin[10];
                    cvt_in(BUFA(tn), BUFB(tn), BUFC(tn), xin);
                    compute_gi<10>(w, xin, A0, Gn0);
                    gru_tail<10>(w, whhr, A1, Gn1, h);
                    fscrA[t+1] = h4pack(__floats2half2_rn(h[0], h[1]), __floats2half2_rn(h[2], h[3]));
                    fscrC[t+1] = h2pack(h[4], 0.f);
                }
            }
        }
        {   // bwd (descending); reads entry t-1 before overwriting entry t
            const float* w = sw + comboOff(2*l+1);
            load_whh(w, 10, whhr);
#pragma unroll
            for (int u = 0; u < 5; ++u) h[u] = 0.f;
            u64 A0[5], Gn0[3], A1[5], Gn1[3];
            {
                float xin[10];
                cvt_in(BUFA(TSTEPS-1), BUFB(TSTEPS-1), BUFC(TSTEPS-1), xin);
                compute_gi<10>(w, xin, A0, Gn0);
            }
#pragma unroll 1
            for (int tt = 0; tt < TSTEPS; tt += 2) {
                int t = TSTEPS-1-tt;                        // t >= 1
                {   // position t
                    u64 fa = fscrA[t]; u32 fc = fscrC[t];
                    float xin[10];
                    cvt_in(BUFA(t-1), BUFB(t-1), BUFC(t-1), xin);
                    compute_gi<10>(w, xin, A1, Gn1);
                    gru_tail<10>(w, whhr, A0, Gn0, h);
                    WRITE_ENTRY(t, fa, fc);
                }
                {   // position t-1
                    int tn = (t-2 >= 0) ? t-2 : 0;
                    u64 fa = fscrA[t-1]; u32 fc = fscrC[t-1];
                    float xin[10];
                    cvt_in(BUFA(tn), BUFB(tn), BUFC(tn), xin);
                    compute_gi<10>(w, xin, A0, Gn0);
                    gru_tail<10>(w, whhr, A1, Gn1, h);
                    WRITE_ENTRY(t-1, fa, fc);
                }
            }
        }
    }

    // ===== layer 4: fwd full (pipelined, keep final h only); bwd = ONE step =====
    float hf[5];
    {
        const float* w = sw + comboOff(8);
        load_whh(w, 10, whhr);
#pragma unroll
        for (int u = 0; u < 5; ++u) h[u] = 0.f;
        u64 A0[5], Gn0[3], A1[5], Gn1[3];
        {
            float xin[10];
            cvt_in(BUFA(0), BUFB(0), BUFC(0), xin);
            compute_gi<10>(w, xin, A0, Gn0);
        }
#pragma unroll 1
        for (int t = 0; t < TSTEPS; t += 2) {
            {
                float xin[10];
                cvt_in(BUFA(t+1), BUFB(t+1), BUFC(t+1), xin);
                compute_gi<10>(w, xin, A1, Gn1);
                gru_tail<10>(w, whhr, A0, Gn0, h);
            }
            {
                int tn = (t+2 < TSTEPS) ? t+2 : TSTEPS-1;
                float xin[10];
                cvt_in(BUFA(tn), BUFB(tn), BUFC(tn), xin);
                compute_gi<10>(w, xin, A0, Gn0);
                gru_tail<10>(w, whhr, A1, Gn1, h);
            }
        }
#pragma unroll
        for (int u = 0; u < 5; ++u) hf[u] = h[u];
    }
    {
        const float* w = sw + comboOff(9);
        load_whh(w, 10, whhr);
#pragma unroll
        for (int u = 0; u < 5; ++u) h[u] = 0.f;
        float xin[10];
        int t = TSTEPS-1;
        cvt_in(BUFA(t), BUFB(t), BUFC(t), xin);
        u64 A[5], Gn[3];
        compute_gi<10>(w, xin, A, Gn);
        gru_tail<10>(w, whhr, A, Gn, h);
    }

    float2* o2 = (float2*)(out + (size_t)b*10);
    o2[0] = make_float2(hf[0], hf[1]);
    o2[1] = make_float2(hf[2], hf[3]);
    o2[2] = make_float2(hf[4], h[0]);
    o2[3] = make_float2(h[1],  h[2]);
    o2[4] = make_float2(h[3],  h[4]);
}

extern "C" void kernel_launch(void* const* d_in, const int* in_sizes, int n_in,
                              void* d_out, int out_size)
{
    (void)in_sizes; (void)n_in; (void)out_size;
    // 9728 (weights) + 30*64*(8+8+4) = 48128 B -> 4 blocks/SM (R5 config)
    const size_t smem = (size_t)WTOT*4 + (size_t)TSTEPS*BLOCK*(8+8+4);
    cudaFuncSetAttribute(gru_kernel, cudaFuncAttributeMaxDynamicSharedMemorySize, (int)smem);
    gru_kernel<<<NBATCH/BLOCK, BLOCK, smem>>>(
        (const float*)d_in[0],
        (const float*)d_in[1], (const float*)d_in[2],
        (const float*)d_in[3], (const float*)d_in[4],
        (const float*)d_in[5], (const float*)d_in[6],
        (const float*)d_in[7], (const float*)d_in[8],
        (float*)d_out);
}